// round 7
// baseline (speedup 1.0000x reference)
#include <cuda_runtime.h>
#include <cuda_bf16.h>
#include <cuda_fp16.h>
#include <cstdint>

// Problem shape (fixed by the dataset)
#define BATCH 8
#define LSEQ  2048
#define DDIM  1024
#define TAW_INV 50.0f

// int8 quantization scale: clip at 4.54 sigma, quant dot-error sigma ~0.46
#define QS   28.0f
#define SCI  (1.0f / (QS * QS))          // s32 dot -> float dot

// Scratch (static __device__ arrays — allocation-free rule)
__device__ int8_t g_Q8[(size_t)BATCH * LSEQ * DDIM];          // 16.8 MB
__device__ int8_t g_M8[(size_t)BATCH * LSEQ * DDIM];          // 16.8 MB
__device__ __half g_S [(size_t)BATCH * LSEQ * LSEQ];          // 67 MB (approx dots)

// ---------------------------------------------------------------------------
// Helpers
// ---------------------------------------------------------------------------
__device__ __forceinline__ uint32_t smem_u32(const void* p) {
    uint32_t a;
    asm("{ .reg .u64 t; cvta.to.shared.u64 t, %1; cvt.u32.u64 %0, t; }"
        : "=r"(a) : "l"(p));
    return a;
}

__device__ __forceinline__ void cp_async16(uint32_t saddr, const void* gptr) {
    asm volatile("cp.async.cg.shared.global [%0], [%1], 16;\n" :: "r"(saddr), "l"(gptr));
}

#define LDSM_X4(r, addr) \
    asm volatile("ldmatrix.sync.aligned.m8n8.x4.shared.b16 {%0,%1,%2,%3}, [%4];" \
        : "=r"((r)[0]), "=r"((r)[1]), "=r"((r)[2]), "=r"((r)[3]) : "r"(addr))

// int8 MMA: m16n8k32, s32 accumulators (exact integer accumulation)
#define MMAI8(d, a, b)                                                        \
    asm volatile(                                                             \
        "mma.sync.aligned.m16n8k32.row.col.s32.s8.s8.s32 "                    \
        "{%0,%1,%2,%3}, {%4,%5,%6,%7}, {%8,%9}, {%0,%1,%2,%3};\n"             \
        : "+r"((d)[0]), "+r"((d)[1]), "+r"((d)[2]), "+r"((d)[3])              \
        : "r"((a)[0]), "r"((a)[1]), "r"((a)[2]), "r"((a)[3]),                 \
          "r"((b)[0]), "r"((b)[1]))

__device__ __forceinline__ uint32_t pack4(float4 v) {
    int a = __float2int_rn(fminf(fmaxf(v.x * QS, -127.f), 127.f));
    int b = __float2int_rn(fminf(fmaxf(v.y * QS, -127.f), 127.f));
    int c = __float2int_rn(fminf(fmaxf(v.z * QS, -127.f), 127.f));
    int d = __float2int_rn(fminf(fmaxf(v.w * QS, -127.f), 127.f));
    return (uint32_t)(a & 255) | ((uint32_t)(b & 255) << 8) |
           ((uint32_t)(c & 255) << 16) | ((uint32_t)(d & 255) << 24);
}

// ---------------------------------------------------------------------------
// Kernel 1: fp32 -> int8 quantization of query and memory
// ---------------------------------------------------------------------------
__global__ void convert_kernel(const float* __restrict__ q, const float* __restrict__ m) {
    size_t i = (size_t)blockIdx.x * blockDim.x + threadIdx.x;   // 8-float groups
    size_t n8 = (size_t)BATCH * LSEQ * DDIM / 8;
    if (i >= n8) return;
    const float4* q4 = (const float4*)q;
    const float4* m4 = (const float4*)m;
    uint2 vq = make_uint2(pack4(q4[2*i]), pack4(q4[2*i+1]));
    uint2 vm = make_uint2(pack4(m4[2*i]), pack4(m4[2*i+1]));
    ((uint2*)g_Q8)[i] = vq;
    ((uint2*)g_M8)[i] = vm;
}

// ---------------------------------------------------------------------------
// Kernel 2: int8 mma.sync GEMM, 128x128 tile, BK=64 (bytes), 4-stage cp.async,
// ldmatrix fragment loads, 2 CTAs/SM. S[b,q,k] = dot(Q,M)/QS^2 stored fp16.
// ---------------------------------------------------------------------------
#define BM 128
#define BN 128
#define BKB 64                             // k-bytes (int8 elems) per stage
#define PITCH_B 80                         // bytes per smem row (64 used + 16 pad)
#define STG_SZ  (BM * PITCH_B)             // 10240 B per operand stage
#define NSTG 4
#define NKB (DDIM / BKB)                   // 16
#define QK_DSMEM (2 * NSTG * STG_SZ)       // 81920 B

__global__ __launch_bounds__(256, 2) void qk_gemm_kernel() {
    extern __shared__ __align__(16) char dsm[];
    const uint32_t sb = smem_u32(dsm);

    const int tid   = threadIdx.x;
    const int lane  = tid & 31;
    const int warp  = tid >> 5;
    const int warpM = warp >> 2;           // 0..1  -> 64-row stripe
    const int warpN = warp & 3;            // 0..3  -> 32-col stripe
    const int g     = lane >> 2;
    const int t     = lane & 3;

    const int b     = blockIdx.z;
    const int mBase = blockIdx.y * BM;
    const int nBase = blockIdx.x * BN;
    const int8_t* Qb = g_Q8 + (size_t)b * LSEQ * DDIM;
    const int8_t* Mb = g_M8 + (size_t)b * LSEQ * DDIM;

    uint32_t aS[NSTG], bS[NSTG];
    #pragma unroll
    for (int s = 0; s < NSTG; s++) {
        aS[s] = sb + s * STG_SZ;
        bS[s] = sb + NSTG * STG_SZ + s * STG_SZ;
    }

    // ldmatrix per-thread addressing (byte layout identical to b16 case)
    const int rowA  = warpM * 64 + (lane & 7) + ((lane >> 3) & 1) * 8;
    const int colAb = ((lane >> 4) & 1) * 16;        // byte offset
    const int rowB  = warpN * 32 + (lane & 7) + ((lane >> 4) & 1) * 8;
    const int colBb = ((lane >> 3) & 1) * 16;

    int32_t acc[4][4][4];
    #pragma unroll
    for (int i = 0; i < 4; i++)
        #pragma unroll
        for (int j = 0; j < 4; j++)
            #pragma unroll
            for (int r = 0; r < 4; r++) acc[i][j][r] = 0;

    auto load_stage = [&](int s, int kb) {
        int k0 = kb * BKB;                           // byte offset along k
        #pragma unroll
        for (int i = 0; i < 2; i++) {                // 512 chunks per operand
            int j = tid + i * 256;
            int row = j >> 2;
            int c16 = (j & 3) * 16;
            cp_async16(aS[s] + row * PITCH_B + c16,
                       Qb + (size_t)(mBase + row) * DDIM + k0 + c16);
            cp_async16(bS[s] + row * PITCH_B + c16,
                       Mb + (size_t)(nBase + row) * DDIM + k0 + c16);
        }
        asm volatile("cp.async.commit_group;\n");
    };

    // prologue: 3 stages in flight
    load_stage(0, 0);
    load_stage(1, 1);
    load_stage(2, 2);

    for (int kb = 0; kb < NKB; kb++) {
        int s = kb & (NSTG - 1);
        if (kb < NKB - 2)       asm volatile("cp.async.wait_group 2;\n");
        else if (kb == NKB - 2) asm volatile("cp.async.wait_group 1;\n");
        else                    asm volatile("cp.async.wait_group 0;\n");
        __syncthreads();

        if (kb + 3 < NKB) load_stage((kb + 3) & (NSTG - 1), kb + 3);

        uint32_t aBase = aS[s] + rowA * PITCH_B + colAb;
        uint32_t bBase = bS[s] + rowB * PITCH_B + colBb;
        #pragma unroll
        for (int ks = 0; ks < 2; ks++) {             // two k32 slabs per 64B row
            uint32_t af[4][4], bf[2][4];
            #pragma unroll
            for (int mt = 0; mt < 4; mt++)
                LDSM_X4(af[mt], aBase + mt * (16 * PITCH_B) + ks * 32);
            #pragma unroll
            for (int n2 = 0; n2 < 2; n2++)
                LDSM_X4(bf[n2], bBase + n2 * (16 * PITCH_B) + ks * 32);
            #pragma unroll
            for (int mt = 0; mt < 4; mt++)
                #pragma unroll
                for (int nt = 0; nt < 4; nt++)
                    MMAI8(acc[mt][nt], af[mt], &bf[nt >> 1][(nt & 1) * 2]);
        }
    }

    // Epilogue: s32 -> float dot -> fp16 (same thread mapping as validated kernel)
    __half* Srow = g_S + (size_t)b * LSEQ * LSEQ;
    #pragma unroll
    for (int mt = 0; mt < 4; mt++) {
        #pragma unroll
        for (int nt = 0; nt < 4; nt++) {
            int row = mBase + warpM * 64 + mt * 16 + g;
            int col = nBase + warpN * 32 + nt * 8 + 2 * t;
            *(half2*)(Srow + (size_t)(row    ) * LSEQ + col) =
                __floats2half2_rn((float)acc[mt][nt][0] * SCI,
                                  (float)acc[mt][nt][1] * SCI);
            *(half2*)(Srow + (size_t)(row + 8) * LSEQ + col) =
                __floats2half2_rn((float)acc[mt][nt][2] * SCI,
                                  (float)acc[mt][nt][3] * SCI);
        }
    }
}

// ---------------------------------------------------------------------------
// Kernel 3: per-row refine. Margin covers int8 quant error (sigma~0.46 dots).
// nc==1 fast path (exact: residual mass < e^-100). nc>1: warp-parallel exact
// fp32 dots + exact softmax mixture.
// ---------------------------------------------------------------------------
#define CAP 64
#define MARGIN 3.0f

__global__ __launch_bounds__(256) void refine_kernel(const float* __restrict__ Q,
                                                     const float* __restrict__ Mem,
                                                     float* __restrict__ Out) {
    const int b = blockIdx.y, q = blockIdx.x, tid = threadIdx.x;
    const int lane = tid & 31, warp = tid >> 5;
    const __half* srow = g_S + ((size_t)b * LSEQ + q) * LSEQ;

    __shared__ float red[8];
    __shared__ int   s_cnt;
    __shared__ int   s_idx[CAP];
    __shared__ float s_dot[CAP];
    __shared__ float s_w[CAP];
    __shared__ float s_max;

    // 1) row max of approx scores
    float mx = -1e30f;
    for (int k = tid; k < LSEQ; k += 256) mx = fmaxf(mx, __half2float(srow[k]));
    #pragma unroll
    for (int o = 16; o; o >>= 1) mx = fmaxf(mx, __shfl_xor_sync(0xffffffffu, mx, o));
    if (lane == 0) red[warp] = mx;
    __syncthreads();
    if (tid < 32) {
        float v = (tid < 8) ? red[tid] : -1e30f;
        #pragma unroll
        for (int o = 4; o; o >>= 1) v = fmaxf(v, __shfl_xor_sync(0xffffffffu, v, o));
        if (tid == 0) { s_max = v; s_cnt = 0; }
    }
    __syncthreads();

    // 2) candidates within margin of approx max
    float thr = s_max - MARGIN;
    for (int k = tid; k < LSEQ; k += 256) {
        if (__half2float(srow[k]) >= thr) {
            int p = atomicAdd(&s_cnt, 1);
            if (p < CAP) s_idx[p] = k;
        }
    }
    __syncthreads();
    int nc = min(s_cnt, CAP);

    // 3) fast path: single candidate -> output = that memory row exactly
    if (nc == 1) {
        const float4* src = (const float4*)(Mem + ((size_t)b * LSEQ + s_idx[0]) * DDIM);
        float4* dst = (float4*)(Out + ((size_t)b * LSEQ + q) * DDIM);
        dst[tid] = src[tid];                     // 256 threads x float4 = 1024
        return;
    }

    if (tid == 0) {                              // sort for determinism
        for (int i = 1; i < nc; i++) {
            int v = s_idx[i], j = i - 1;
            while (j >= 0 && s_idx[j] > v) { s_idx[j + 1] = s_idx[j]; j--; }
            s_idx[j + 1] = v;
        }
    }
    __syncthreads();

    // 4) exact fp32 dots, one warp per candidate
    const float* qrow = Q + ((size_t)b * LSEQ + q) * DDIM;
    for (int j = warp; j < nc; j += 8) {
        const float* mrow = Mem + ((size_t)b * LSEQ + s_idx[j]) * DDIM;
        float p = 0.f;
        #pragma unroll 4
        for (int d = lane; d < DDIM; d += 32) p += qrow[d] * mrow[d];
        #pragma unroll
        for (int o = 16; o; o >>= 1) p += __shfl_xor_sync(0xffffffffu, p, o);
        if (lane == 0) s_dot[j] = p;
    }
    __syncthreads();

    // 5) exact softmax over candidates
    if (tid == 0) {
        float dm = -1e30f;
        for (int j = 0; j < nc; j++) dm = fmaxf(dm, s_dot[j]);
        float sum = 0.f;
        for (int j = 0; j < nc; j++) {
            float w = expf((s_dot[j] - dm) * TAW_INV);
            s_w[j] = w; sum += w;
        }
        float inv = 1.0f / sum;
        for (int j = 0; j < nc; j++) s_w[j] *= inv;
    }
    __syncthreads();

    // 6) output mixture (float4 vectorized)
    const float4* M4 = (const float4*)Mem;
    float4* dst = (float4*)(Out + ((size_t)b * LSEQ + q) * DDIM);
    float4 a = make_float4(0.f, 0.f, 0.f, 0.f);
    for (int j = 0; j < nc; j++) {
        float w = s_w[j];
        float4 v = M4[(((size_t)b * LSEQ + s_idx[j]) * DDIM >> 2) + tid];
        a.x += w * v.x; a.y += w * v.y; a.z += w * v.z; a.w += w * v.w;
    }
    dst[tid] = a;
}

// ---------------------------------------------------------------------------
extern "C" void kernel_launch(void* const* d_in, const int* in_sizes, int n_in,
                              void* d_out, int out_size) {
    const float* q = (const float*)d_in[0];
    const float* m = (const float*)d_in[1];
    float* out = (float*)d_out;

    // Host-side attribute set (not a stream op -> capture-safe)
    cudaFuncSetAttribute(qk_gemm_kernel,
                         cudaFuncAttributeMaxDynamicSharedMemorySize, QK_DSMEM);

    size_t n8 = (size_t)BATCH * LSEQ * DDIM / 8;   // 2,097,152
    convert_kernel<<<(unsigned)((n8 + 255) / 256), 256>>>(q, m);

    dim3 gg(LSEQ / BN, LSEQ / BM, BATCH);          // 16 x 16 x 8
    qk_gemm_kernel<<<gg, 256, QK_DSMEM>>>();

    dim3 rg(LSEQ, BATCH);
    refine_kernel<<<rg, 256>>>(q, m, out);
}

// round 8
// speedup vs baseline: 1.6273x; 1.6273x over previous
#include <cuda_runtime.h>
#include <cuda_bf16.h>
#include <cuda_fp16.h>
#include <cstdint>

// Problem shape (fixed by the dataset)
#define BATCH 8
#define LSEQ  2048
#define DDIM  1024
#define TAW_INV 50.0f

// Scratch (static __device__ arrays — allocation-free rule)
__device__ __half g_Qh[(size_t)BATCH * LSEQ * DDIM];          // 33.5 MB
__device__ __half g_Mh[(size_t)BATCH * LSEQ * DDIM];          // 33.5 MB
__device__ __half g_S [(size_t)BATCH * LSEQ * LSEQ];          // 67 MB (approx dots)

// ---------------------------------------------------------------------------
// Helpers
// ---------------------------------------------------------------------------
__device__ __forceinline__ uint32_t smem_u32(const void* p) {
    uint32_t a;
    asm("{ .reg .u64 t; cvta.to.shared.u64 t, %1; cvt.u32.u64 %0, t; }"
        : "=r"(a) : "l"(p));
    return a;
}

__device__ __forceinline__ void cp_async16(uint32_t saddr, const void* gptr) {
    asm volatile("cp.async.cg.shared.global [%0], [%1], 16;\n" :: "r"(saddr), "l"(gptr));
}

#define LDSM_X4(r, addr) \
    asm volatile("ldmatrix.sync.aligned.m8n8.x4.shared.b16 {%0,%1,%2,%3}, [%4];" \
        : "=r"((r)[0]), "=r"((r)[1]), "=r"((r)[2]), "=r"((r)[3]) : "r"(addr))

// fp16 MMA with fp16 accumulators (full-rate HMMA path)
#define MMAF16(d, a, b)                                                       \
    asm volatile(                                                             \
        "mma.sync.aligned.m16n8k16.row.col.f16.f16.f16.f16 "                  \
        "{%0,%1}, {%2,%3,%4,%5}, {%6,%7}, {%0,%1};\n"                         \
        : "+r"((d)[0]), "+r"((d)[1])                                          \
        : "r"((a)[0]), "r"((a)[1]), "r"((a)[2]), "r"((a)[3]),                 \
          "r"((b)[0]), "r"((b)[1]))

// ---------------------------------------------------------------------------
// Kernel 1: fp32 -> fp16 conversion of query and memory
// ---------------------------------------------------------------------------
__global__ void convert_kernel(const float* __restrict__ q, const float* __restrict__ m) {
    size_t i = (size_t)blockIdx.x * blockDim.x + threadIdx.x;   // float4 groups
    size_t n4 = (size_t)BATCH * LSEQ * DDIM / 4;
    if (i >= n4) return;
    float4 vq = ((const float4*)q)[i];
    float4 vm = ((const float4*)m)[i];
    __half2* Q2 = (__half2*)g_Qh;
    __half2* M2 = (__half2*)g_Mh;
    Q2[2*i]   = __floats2half2_rn(vq.x, vq.y);
    Q2[2*i+1] = __floats2half2_rn(vq.z, vq.w);
    M2[2*i]   = __floats2half2_rn(vm.x, vm.y);
    M2[2*i+1] = __floats2half2_rn(vm.z, vm.w);
}

// ---------------------------------------------------------------------------
// Kernel 2: fp16 mma.sync GEMM (f16 accumulate), 128x128 tile, BK=32,
// 4-stage cp.async, ldmatrix fragment loads, 2 CTAs/SM.
// S[b,q,k] = dot(Q[b,q,:], M[b,k,:]) stored fp16 (raw dots).
// ---------------------------------------------------------------------------
#define BM 128
#define BN 128
#define BK 32
#define PITCH_B 80                         // bytes per smem row (64 used + 16 pad)
#define STG_SZ  (BM * PITCH_B)             // 10240 B per operand stage
#define NSTG 4
#define NKB (DDIM / BK)                    // 32
#define QK_DSMEM (2 * NSTG * STG_SZ)       // 81920 B

__global__ __launch_bounds__(256, 2) void qk_gemm_kernel() {
    extern __shared__ __align__(16) char dsm[];
    const uint32_t sb = smem_u32(dsm);

    const int tid   = threadIdx.x;
    const int lane  = tid & 31;
    const int warp  = tid >> 5;
    const int warpM = warp >> 2;           // 0..1  -> 64-row stripe
    const int warpN = warp & 3;            // 0..3  -> 32-col stripe
    const int g     = lane >> 2;
    const int t     = lane & 3;

    const int b     = blockIdx.z;
    const int mBase = blockIdx.y * BM;
    const int nBase = blockIdx.x * BN;
    const __half* Qb = g_Qh + (size_t)b * LSEQ * DDIM;
    const __half* Mb = g_Mh + (size_t)b * LSEQ * DDIM;

    uint32_t aS[NSTG], bS[NSTG];
    #pragma unroll
    for (int s = 0; s < NSTG; s++) {
        aS[s] = sb + s * STG_SZ;
        bS[s] = sb + NSTG * STG_SZ + s * STG_SZ;
    }

    // ldmatrix per-thread base offsets (validated mapping)
    const int rowA = warpM * 64 + (lane & 7) + ((lane >> 3) & 1) * 8;
    const int colA = ((lane >> 4) & 1) * 8;          // k-elems
    const int rowB = warpN * 32 + (lane & 7) + ((lane >> 4) & 1) * 8;
    const int colB = ((lane >> 3) & 1) * 8;

    uint32_t acc[4][4][2];                 // f16x2 accumulators (raw dots)
    #pragma unroll
    for (int i = 0; i < 4; i++)
        #pragma unroll
        for (int j = 0; j < 4; j++) { acc[i][j][0] = 0u; acc[i][j][1] = 0u; }

    auto load_stage = [&](int s, int kb) {
        int k0 = kb * BK;
        #pragma unroll
        for (int i = 0; i < 2; i++) {                // 512 chunks per operand
            int j = tid + i * 256;
            int row = j >> 2;
            int c16 = (j & 3) * 16;                  // byte col
            cp_async16(aS[s] + row * PITCH_B + c16,
                       Qb + (size_t)(mBase + row) * DDIM + k0 + c16 / 2);
            cp_async16(bS[s] + row * PITCH_B + c16,
                       Mb + (size_t)(nBase + row) * DDIM + k0 + c16 / 2);
        }
        asm volatile("cp.async.commit_group;\n");
    };

    // prologue: 3 stages in flight
    load_stage(0, 0);
    load_stage(1, 1);
    load_stage(2, 2);

    for (int kb = 0; kb < NKB; kb++) {
        int s = kb & (NSTG - 1);
        if (kb < NKB - 2)       asm volatile("cp.async.wait_group 2;\n");
        else if (kb == NKB - 2) asm volatile("cp.async.wait_group 1;\n");
        else                    asm volatile("cp.async.wait_group 0;\n");
        __syncthreads();

        if (kb + 3 < NKB) load_stage((kb + 3) & (NSTG - 1), kb + 3);

        uint32_t aBase = aS[s] + rowA * PITCH_B + colA * 2;
        uint32_t bBase = bS[s] + rowB * PITCH_B + colB * 2;
        #pragma unroll
        for (int ks = 0; ks < 2; ks++) {             // two k16 slabs
            uint32_t af[4][4], bf[2][4];
            #pragma unroll
            for (int mt = 0; mt < 4; mt++)
                LDSM_X4(af[mt], aBase + mt * (16 * PITCH_B) + ks * 32);
            #pragma unroll
            for (int n2 = 0; n2 < 2; n2++)
                LDSM_X4(bf[n2], bBase + n2 * (16 * PITCH_B) + ks * 32);
            #pragma unroll
            for (int mt = 0; mt < 4; mt++)
                #pragma unroll
                for (int nt = 0; nt < 4; nt++)
                    MMAF16(acc[mt][nt], af[mt], &bf[nt >> 1][(nt & 1) * 2]);
        }
    }

    // Epilogue: accumulators are already fp16 pairs -> direct stores
    __half* Srow = g_S + (size_t)b * LSEQ * LSEQ;
    #pragma unroll
    for (int mt = 0; mt < 4; mt++) {
        #pragma unroll
        for (int nt = 0; nt < 4; nt++) {
            int row = mBase + warpM * 64 + mt * 16 + g;
            int col = nBase + warpN * 32 + nt * 8 + 2 * t;
            *(uint32_t*)(Srow + (size_t)(row    ) * LSEQ + col) = acc[mt][nt][0];
            *(uint32_t*)(Srow + (size_t)(row + 8) * LSEQ + col) = acc[mt][nt][1];
        }
    }
}

// ---------------------------------------------------------------------------
// Kernel 3: per-row refine. fp16 pipeline error sigma ~0.25 dots; margin 1.0
// = 4 sigma + Gumbel spacing 8.2 -> miss prob ~0. nc==1 fast path (exact).
// ---------------------------------------------------------------------------
#define CAP 64
#define MARGIN 1.0f

__global__ __launch_bounds__(256) void refine_kernel(const float* __restrict__ Q,
                                                     const float* __restrict__ Mem,
                                                     float* __restrict__ Out) {
    const int b = blockIdx.y, q = blockIdx.x, tid = threadIdx.x;
    const int lane = tid & 31, warp = tid >> 5;
    const __half* srow = g_S + ((size_t)b * LSEQ + q) * LSEQ;

    __shared__ float red[8];
    __shared__ int   s_cnt;
    __shared__ int   s_idx[CAP];
    __shared__ float s_dot[CAP];
    __shared__ float s_w[CAP];
    __shared__ float s_max;

    // 1) row max of approx scores
    float mx = -1e30f;
    for (int k = tid; k < LSEQ; k += 256) mx = fmaxf(mx, __half2float(srow[k]));
    #pragma unroll
    for (int o = 16; o; o >>= 1) mx = fmaxf(mx, __shfl_xor_sync(0xffffffffu, mx, o));
    if (lane == 0) red[warp] = mx;
    __syncthreads();
    if (tid < 32) {
        float v = (tid < 8) ? red[tid] : -1e30f;
        #pragma unroll
        for (int o = 4; o; o >>= 1) v = fmaxf(v, __shfl_xor_sync(0xffffffffu, v, o));
        if (tid == 0) { s_max = v; s_cnt = 0; }
    }
    __syncthreads();

    // 2) candidates within margin of approx max
    float thr = s_max - MARGIN;
    for (int k = tid; k < LSEQ; k += 256) {
        if (__half2float(srow[k]) >= thr) {
            int p = atomicAdd(&s_cnt, 1);
            if (p < CAP) s_idx[p] = k;
        }
    }
    __syncthreads();
    int nc = min(s_cnt, CAP);

    // 3) fast path: single candidate -> output = that memory row exactly
    if (nc == 1) {
        const float4* src = (const float4*)(Mem + ((size_t)b * LSEQ + s_idx[0]) * DDIM);
        float4* dst = (float4*)(Out + ((size_t)b * LSEQ + q) * DDIM);
        dst[tid] = src[tid];                     // 256 threads x float4 = 1024
        return;
    }

    if (tid == 0) {                              // sort for determinism
        for (int i = 1; i < nc; i++) {
            int v = s_idx[i], j = i - 1;
            while (j >= 0 && s_idx[j] > v) { s_idx[j + 1] = s_idx[j]; j--; }
            s_idx[j + 1] = v;
        }
    }
    __syncthreads();

    // 4) exact fp32 dots, one warp per candidate
    const float* qrow = Q + ((size_t)b * LSEQ + q) * DDIM;
    for (int j = warp; j < nc; j += 8) {
        const float* mrow = Mem + ((size_t)b * LSEQ + s_idx[j]) * DDIM;
        float p = 0.f;
        #pragma unroll 4
        for (int d = lane; d < DDIM; d += 32) p += qrow[d] * mrow[d];
        #pragma unroll
        for (int o = 16; o; o >>= 1) p += __shfl_xor_sync(0xffffffffu, p, o);
        if (lane == 0) s_dot[j] = p;
    }
    __syncthreads();

    // 5) exact softmax over candidates
    if (tid == 0) {
        float dm = -1e30f;
        for (int j = 0; j < nc; j++) dm = fmaxf(dm, s_dot[j]);
        float sum = 0.f;
        for (int j = 0; j < nc; j++) {
            float w = expf((s_dot[j] - dm) * TAW_INV);
            s_w[j] = w; sum += w;
        }
        float inv = 1.0f / sum;
        for (int j = 0; j < nc; j++) s_w[j] *= inv;
    }
    __syncthreads();

    // 6) output mixture (float4 vectorized)
    const float4* M4 = (const float4*)Mem;
    float4* dst = (float4*)(Out + ((size_t)b * LSEQ + q) * DDIM);
    float4 a = make_float4(0.f, 0.f, 0.f, 0.f);
    for (int j = 0; j < nc; j++) {
        float w = s_w[j];
        float4 v = M4[(((size_t)b * LSEQ + s_idx[j]) * DDIM >> 2) + tid];
        a.x += w * v.x; a.y += w * v.y; a.z += w * v.z; a.w += w * v.w;
    }
    dst[tid] = a;
}

// ---------------------------------------------------------------------------
extern "C" void kernel_launch(void* const* d_in, const int* in_sizes, int n_in,
                              void* d_out, int out_size) {
    const float* q = (const float*)d_in[0];
    const float* m = (const float*)d_in[1];
    float* out = (float*)d_out;

    // Host-side attribute set (not a stream op -> capture-safe)
    cudaFuncSetAttribute(qk_gemm_kernel,
                         cudaFuncAttributeMaxDynamicSharedMemorySize, QK_DSMEM);

    size_t n4 = (size_t)BATCH * LSEQ * DDIM / 4;   // 4,194,304
    convert_kernel<<<(unsigned)((n4 + 255) / 256), 256>>>(q, m);

    dim3 gg(LSEQ / BN, LSEQ / BM, BATCH);          // 16 x 16 x 8
    qk_gemm_kernel<<<gg, 256, QK_DSMEM>>>();

    dim3 rg(LSEQ, BATCH);
    refine_kernel<<<rg, 256>>>(q, m, out);
}

// round 10
// speedup vs baseline: 1.8433x; 1.1328x over previous
#include <cuda_runtime.h>
#include <cuda_bf16.h>
#include <cuda_fp16.h>
#include <cstdint>

// Problem shape (fixed by the dataset)
#define BATCH 8
#define LSEQ  2048
#define DDIM  1024
#define TAW_INV 50.0f

// Scratch (static __device__ arrays — allocation-free rule)
__device__ __half    g_Qh[(size_t)BATCH * LSEQ * DDIM];       // 33.5 MB
__device__ __half    g_Mh[(size_t)BATCH * LSEQ * DDIM];       // 33.5 MB
__device__ __half    g_S [(size_t)BATCH * LSEQ * LSEQ];       // 67 MB (approx dots)
__device__ uint32_t  g_rowmax[(size_t)BATCH * LSEQ];          // order-keyed row max

// ---------------------------------------------------------------------------
// Helpers
// ---------------------------------------------------------------------------
__device__ __forceinline__ uint32_t smem_u32(const void* p) {
    uint32_t a;
    asm("{ .reg .u64 t; cvta.to.shared.u64 t, %1; cvt.u32.u64 %0, t; }"
        : "=r"(a) : "l"(p));
    return a;
}

__device__ __forceinline__ void cp_async16(uint32_t saddr, const void* gptr) {
    asm volatile("cp.async.cg.shared.global [%0], [%1], 16;\n" :: "r"(saddr), "l"(gptr));
}

#define LDSM_X4(r, addr) \
    asm volatile("ldmatrix.sync.aligned.m8n8.x4.shared.b16 {%0,%1,%2,%3}, [%4];" \
        : "=r"((r)[0]), "=r"((r)[1]), "=r"((r)[2]), "=r"((r)[3]) : "r"(addr))

// fp16 MMA with fp16 accumulators
#define MMAF16(d, a, b)                                                       \
    asm volatile(                                                             \
        "mma.sync.aligned.m16n8k16.row.col.f16.f16.f16.f16 "                  \
        "{%0,%1}, {%2,%3,%4,%5}, {%6,%7}, {%0,%1};\n"                         \
        : "+r"((d)[0]), "+r"((d)[1])                                          \
        : "r"((a)[0]), "r"((a)[1]), "r"((a)[2]), "r"((a)[3]),                 \
          "r"((b)[0]), "r"((b)[1]))

// Order-preserving float <-> uint key (unsigned compare == float compare)
__device__ __forceinline__ uint32_t fkey(float f) {
    uint32_t b = __float_as_uint(f);
    return (b & 0x80000000u) ? ~b : (b | 0x80000000u);
}
__device__ __forceinline__ float funkey(uint32_t k) {
    uint32_t b = (k & 0x80000000u) ? (k & 0x7FFFFFFFu) : ~k;
    return __uint_as_float(b);
}

// ---------------------------------------------------------------------------
// Kernel 1: fp32 -> fp16 conversion + rowmax init
// ---------------------------------------------------------------------------
__global__ void convert_kernel(const float* __restrict__ q, const float* __restrict__ m) {
    size_t i = (size_t)blockIdx.x * blockDim.x + threadIdx.x;   // float4 groups
    size_t n4 = (size_t)BATCH * LSEQ * DDIM / 4;
    if (i >= n4) return;
    if (i < (size_t)BATCH * LSEQ) g_rowmax[i] = 0u;   // key(0) < key(any finite)
    float4 vq = ((const float4*)q)[i];
    float4 vm = ((const float4*)m)[i];
    __half2* Q2 = (__half2*)g_Qh;
    __half2* M2 = (__half2*)g_Mh;
    Q2[2*i]   = __floats2half2_rn(vq.x, vq.y);
    Q2[2*i+1] = __floats2half2_rn(vq.z, vq.w);
    M2[2*i]   = __floats2half2_rn(vm.x, vm.y);
    M2[2*i+1] = __floats2half2_rn(vm.z, vm.w);
}

// ---------------------------------------------------------------------------
// Kernel 2: fp16 mma.sync GEMM (f16 acc), CTA tile 128x256, warp tile 64x64,
// BK=32, 3-stage cp.async, ldmatrix, 2 CTAs/SM. Fused row-max atomic.
// ---------------------------------------------------------------------------
#define BM 128
#define BN 256
#define BK 32
#define PITCH_B 80                         // bytes per smem row (64 used + 16 pad)
#define A_STG (BM * PITCH_B)               // 10240
#define B_STG (BN * PITCH_B)               // 20480
#define NSTG 3
#define NKB (DDIM / BK)                    // 32
#define QK_DSMEM (NSTG * (A_STG + B_STG)) // 92160 B

__global__ __launch_bounds__(256, 2) void qk_gemm_kernel() {
    extern __shared__ __align__(16) char dsm[];
    const uint32_t sb = smem_u32(dsm);

    const int tid   = threadIdx.x;
    const int lane  = tid & 31;
    const int warp  = tid >> 5;
    const int warpM = warp & 1;            // 2 stripes of 64 rows
    const int warpN = warp >> 1;           // 4 stripes of 64 cols
    const int g     = lane >> 2;
    const int t     = lane & 3;

    const int b     = blockIdx.z;
    const int mBase = blockIdx.y * BM;
    const int nBase = blockIdx.x * BN;
    const __half* Qb = g_Qh + (size_t)b * LSEQ * DDIM;
    const __half* Mb = g_Mh + (size_t)b * LSEQ * DDIM;

    uint32_t aS[NSTG], bS[NSTG];
    #pragma unroll
    for (int s = 0; s < NSTG; s++) {
        aS[s] = sb + s * (A_STG + B_STG);
        bS[s] = aS[s] + A_STG;
    }

    // ldmatrix per-thread base offsets
    const int rowA = warpM * 64 + (lane & 7) + ((lane >> 3) & 1) * 8;
    const int colA = ((lane >> 4) & 1) * 8;          // k-elems
    const int rowB = warpN * 64 + (lane & 7) + ((lane >> 4) & 1) * 8;
    const int colB = ((lane >> 3) & 1) * 8;

    uint32_t acc[4][8][2];                 // f16x2 accumulators (raw dots)
    #pragma unroll
    for (int i = 0; i < 4; i++)
        #pragma unroll
        for (int j = 0; j < 8; j++) { acc[i][j][0] = 0u; acc[i][j][1] = 0u; }

    auto load_stage = [&](int s, int kb) {
        int k0 = kb * BK;
        #pragma unroll
        for (int i = 0; i < 2; i++) {                // A: 512 16B-chunks
            int j = tid + i * 256;
            int row = j >> 2;
            int c16 = (j & 3) * 16;
            cp_async16(aS[s] + row * PITCH_B + c16,
                       Qb + (size_t)(mBase + row) * DDIM + k0 + c16 / 2);
        }
        #pragma unroll
        for (int i = 0; i < 4; i++) {                // B: 1024 chunks
            int j = tid + i * 256;
            int row = j >> 2;
            int c16 = (j & 3) * 16;
            cp_async16(bS[s] + row * PITCH_B + c16,
                       Mb + (size_t)(nBase + row) * DDIM + k0 + c16 / 2);
        }
        asm volatile("cp.async.commit_group;\n");
    };

    // prologue: 2 stages in flight
    load_stage(0, 0);
    load_stage(1, 1);

    for (int kb = 0; kb < NKB; kb++) {
        int s = kb % NSTG;
        if (kb + 2 < NKB) asm volatile("cp.async.wait_group 1;\n");
        else              asm volatile("cp.async.wait_group 0;\n");
        __syncthreads();

        if (kb + 2 < NKB) load_stage((kb + 2) % NSTG, kb + 2);

        uint32_t aBase = aS[s] + rowA * PITCH_B + colA * 2;
        uint32_t bBase = bS[s] + rowB * PITCH_B + colB * 2;
        #pragma unroll
        for (int ks = 0; ks < 2; ks++) {             // two k16 slabs
            uint32_t af[4][4];
            #pragma unroll
            for (int mt = 0; mt < 4; mt++)
                LDSM_X4(af[mt], aBase + mt * (16 * PITCH_B) + ks * 32);
            #pragma unroll
            for (int nh = 0; nh < 2; nh++) {         // 2 B-halves (32 cols each)
                uint32_t bf[2][4];
                #pragma unroll
                for (int n2 = 0; n2 < 2; n2++)
                    LDSM_X4(bf[n2], bBase + (nh * 32 + n2 * 16) * PITCH_B + ks * 32);
                #pragma unroll
                for (int mt = 0; mt < 4; mt++)
                    #pragma unroll
                    for (int nt = 0; nt < 4; nt++)
                        MMAF16(acc[mt][nh * 4 + nt], af[mt], &bf[nt >> 1][(nt & 1) * 2]);
            }
        }
    }

    // Epilogue: direct fp16 stores + fused row-max (slab max -> global atomicMax)
    __half* Srow = g_S + (size_t)b * LSEQ * LSEQ;
    #pragma unroll
    for (int mt = 0; mt < 4; mt++) {
        float vmax0 = -1e30f, vmax1 = -1e30f;
        #pragma unroll
        for (int j = 0; j < 8; j++) {
            int row = mBase + warpM * 64 + mt * 16 + g;
            int col = nBase + warpN * 64 + j * 8 + 2 * t;
            *(uint32_t*)(Srow + (size_t)(row    ) * LSEQ + col) = acc[mt][j][0];
            *(uint32_t*)(Srow + (size_t)(row + 8) * LSEQ + col) = acc[mt][j][1];
            __half2 v0 = *(__half2*)&acc[mt][j][0];
            __half2 v1 = *(__half2*)&acc[mt][j][1];
            vmax0 = fmaxf(vmax0, fmaxf(__low2float(v0), __high2float(v0)));
            vmax1 = fmaxf(vmax1, fmaxf(__low2float(v1), __high2float(v1)));
        }
        // reduce across the 4 t-threads of each group (same output rows)
        #pragma unroll
        for (int o = 1; o <= 2; o <<= 1) {
            vmax0 = fmaxf(vmax0, __shfl_xor_sync(0xffffffffu, vmax0, o));
            vmax1 = fmaxf(vmax1, __shfl_xor_sync(0xffffffffu, vmax1, o));
        }
        if (t == 0) {
            int row = mBase + warpM * 64 + mt * 16 + g;
            atomicMax(&g_rowmax[(size_t)b * LSEQ + row],     fkey(vmax0));
            atomicMax(&g_rowmax[(size_t)b * LSEQ + row + 8], fkey(vmax1));
        }
    }
}

// ---------------------------------------------------------------------------
// Kernel 3: per-row refine. Row max comes precomputed from the GEMM epilogue
// (bit-consistent with stored fp16 scores). Single candidate scan; nc==1 fast
// path (exact); warp-parallel exact fp32 dots otherwise.
// ---------------------------------------------------------------------------
#define CAP 64
#define MARGIN 1.0f

__global__ __launch_bounds__(256) void refine_kernel(const float* __restrict__ Q,
                                                     const float* __restrict__ Mem,
                                                     float* __restrict__ Out) {
    const int b = blockIdx.y, q = blockIdx.x, tid = threadIdx.x;
    const int lane = tid & 31, warp = tid >> 5;
    const __half* srow = g_S + ((size_t)b * LSEQ + q) * LSEQ;

    __shared__ int   s_cnt;
    __shared__ int   s_idx[CAP];
    __shared__ float s_dot[CAP];
    __shared__ float s_w[CAP];

    if (tid == 0) s_cnt = 0;
    __syncthreads();

    // 1) candidate scan against precomputed row max
    float thr = funkey(g_rowmax[(size_t)b * LSEQ + q]) - MARGIN;
    for (int k = tid; k < LSEQ; k += 256) {
        if (__half2float(srow[k]) >= thr) {
            int p = atomicAdd(&s_cnt, 1);
            if (p < CAP) s_idx[p] = k;
        }
    }
    __syncthreads();
    int nc = min(s_cnt, CAP);

    // 2) fast path: single candidate -> output = that memory row exactly
    if (nc == 1) {
        const float4* src = (const float4*)(Mem + ((size_t)b * LSEQ + s_idx[0]) * DDIM);
        float4* dst = (float4*)(Out + ((size_t)b * LSEQ + q) * DDIM);
        dst[tid] = src[tid];                     // 256 threads x float4 = 1024
        return;
    }

    if (tid == 0) {                              // sort for determinism
        for (int i = 1; i < nc; i++) {
            int v = s_idx[i], j = i - 1;
            while (j >= 0 && s_idx[j] > v) { s_idx[j + 1] = s_idx[j]; j--; }
            s_idx[j + 1] = v;
        }
    }
    __syncthreads();

    // 3) exact fp32 dots, one warp per candidate
    const float* qrow = Q + ((size_t)b * LSEQ + q) * DDIM;
    for (int j = warp; j < nc; j += 8) {
        const float* mrow = Mem + ((size_t)b * LSEQ + s_idx[j]) * DDIM;
        float p = 0.f;
        #pragma unroll 4
        for (int d = lane; d < DDIM; d += 32) p += qrow[d] * mrow[d];
        #pragma unroll
        for (int o = 16; o; o >>= 1) p += __shfl_xor_sync(0xffffffffu, p, o);
        if (lane == 0) s_dot[j] = p;
    }
    __syncthreads();

    // 4) exact softmax over candidates
    if (tid == 0) {
        float dm = -1e30f;
        for (int j = 0; j < nc; j++) dm = fmaxf(dm, s_dot[j]);
        float sum = 0.f;
        for (int j = 0; j < nc; j++) {
            float w = expf((s_dot[j] - dm) * TAW_INV);
            s_w[j] = w; sum += w;
        }
        float inv = 1.0f / sum;
        for (int j = 0; j < nc; j++) s_w[j] *= inv;
    }
    __syncthreads();

    // 5) output mixture (float4 vectorized)
    const float4* M4 = (const float4*)Mem;
    float4* dst = (float4*)(Out + ((size_t)b * LSEQ + q) * DDIM);
    float4 a = make_float4(0.f, 0.f, 0.f, 0.f);
    for (int j = 0; j < nc; j++) {
        float w = s_w[j];
        float4 v = M4[(((size_t)b * LSEQ + s_idx[j]) * DDIM >> 2) + tid];
        a.x += w * v.x; a.y += w * v.y; a.z += w * v.z; a.w += w * v.w;
    }
    dst[tid] = a;
}

// ---------------------------------------------------------------------------
extern "C" void kernel_launch(void* const* d_in, const int* in_sizes, int n_in,
                              void* d_out, int out_size) {
    const float* q = (const float*)d_in[0];
    const float* m = (const float*)d_in[1];
    float* out = (float*)d_out;

    // Host-side attribute set (not a stream op -> capture-safe)
    cudaFuncSetAttribute(qk_gemm_kernel,
                         cudaFuncAttributeMaxDynamicSharedMemorySize, QK_DSMEM);

    size_t n4 = (size_t)BATCH * LSEQ * DDIM / 4;   // 4,194,304
    convert_kernel<<<(unsigned)((n4 + 255) / 256), 256>>>(q, m);

    dim3 gg(LSEQ / BN, LSEQ / BM, BATCH);          // 8 x 16 x 8
    qk_gemm_kernel<<<gg, 256, QK_DSMEM>>>();

    dim3 rg(LSEQ, BATCH);
    refine_kernel<<<rg, 256>>>(q, m, out);
}

// round 11
// speedup vs baseline: 2.1111x; 1.1453x over previous
#include <cuda_runtime.h>
#include <cuda_bf16.h>
#include <cuda_fp16.h>
#include <cstdint>

// Problem shape (fixed by the dataset)
#define BATCH 8
#define LSEQ  2048
#define DDIM  1024
#define TAW_INV 50.0f

// Scratch (static __device__ arrays — allocation-free rule)
__device__ __half g_Qh[(size_t)BATCH * LSEQ * DDIM];          // 33.5 MB
__device__ __half g_Mh[(size_t)BATCH * LSEQ * DDIM];          // 33.5 MB
__device__ __half g_S [(size_t)BATCH * LSEQ * LSEQ];          // 67 MB (approx dots)
__device__ __half g_bmax[(size_t)BATCH * LSEQ * 32];          // per-row per-64col block max (1 MB)

// ---------------------------------------------------------------------------
// Helpers
// ---------------------------------------------------------------------------
__device__ __forceinline__ uint32_t smem_u32(const void* p) {
    uint32_t a;
    asm("{ .reg .u64 t; cvta.to.shared.u64 t, %1; cvt.u32.u64 %0, t; }"
        : "=r"(a) : "l"(p));
    return a;
}

__device__ __forceinline__ void cp_async16(uint32_t saddr, const void* gptr) {
    asm volatile("cp.async.cg.shared.global [%0], [%1], 16;\n" :: "r"(saddr), "l"(gptr));
}

#define LDSM_X4(r, addr) \
    asm volatile("ldmatrix.sync.aligned.m8n8.x4.shared.b16 {%0,%1,%2,%3}, [%4];" \
        : "=r"((r)[0]), "=r"((r)[1]), "=r"((r)[2]), "=r"((r)[3]) : "r"(addr))

// fp16 MMA with fp16 accumulators
#define MMAF16(d, a, b)                                                       \
    asm volatile(                                                             \
        "mma.sync.aligned.m16n8k16.row.col.f16.f16.f16.f16 "                  \
        "{%0,%1}, {%2,%3,%4,%5}, {%6,%7}, {%0,%1};\n"                         \
        : "+r"((d)[0]), "+r"((d)[1])                                          \
        : "r"((a)[0]), "r"((a)[1]), "r"((a)[2]), "r"((a)[3]),                 \
          "r"((b)[0]), "r"((b)[1]))

// ---------------------------------------------------------------------------
// Kernel 1: fp32 -> fp16 conversion
// ---------------------------------------------------------------------------
__global__ void convert_kernel(const float* __restrict__ q, const float* __restrict__ m) {
    size_t i = (size_t)blockIdx.x * blockDim.x + threadIdx.x;   // float4 groups
    size_t n4 = (size_t)BATCH * LSEQ * DDIM / 4;
    if (i >= n4) return;
    float4 vq = ((const float4*)q)[i];
    float4 vm = ((const float4*)m)[i];
    __half2* Q2 = (__half2*)g_Qh;
    __half2* M2 = (__half2*)g_Mh;
    Q2[2*i]   = __floats2half2_rn(vq.x, vq.y);
    Q2[2*i+1] = __floats2half2_rn(vq.z, vq.w);
    M2[2*i]   = __floats2half2_rn(vm.x, vm.y);
    M2[2*i+1] = __floats2half2_rn(vm.z, vm.w);
}

// ---------------------------------------------------------------------------
// Kernel 2: fp16 mma.sync GEMM (f16 acc), CTA tile 128x256, warp tile 64x64,
// BK=32, 3-stage cp.async, ldmatrix, 2 CTAs/SM. Fused per-64col block-max
// stores (no atomics: each warp uniquely owns its (row, ntile) slot).
// ---------------------------------------------------------------------------
#define BM 128
#define BN 256
#define BK 32
#define PITCH_B 80                         // bytes per smem row (64 used + 16 pad)
#define A_STG (BM * PITCH_B)               // 10240
#define B_STG (BN * PITCH_B)               // 20480
#define NSTG 3
#define NKB (DDIM / BK)                    // 32
#define QK_DSMEM (NSTG * (A_STG + B_STG)) // 92160 B

__global__ __launch_bounds__(256, 2) void qk_gemm_kernel() {
    extern __shared__ __align__(16) char dsm[];
    const uint32_t sb = smem_u32(dsm);

    const int tid   = threadIdx.x;
    const int lane  = tid & 31;
    const int warp  = tid >> 5;
    const int warpM = warp & 1;            // 2 stripes of 64 rows
    const int warpN = warp >> 1;           // 4 stripes of 64 cols
    const int g     = lane >> 2;
    const int t     = lane & 3;

    const int b     = blockIdx.z;
    const int mBase = blockIdx.y * BM;
    const int nBase = blockIdx.x * BN;
    const __half* Qb = g_Qh + (size_t)b * LSEQ * DDIM;
    const __half* Mb = g_Mh + (size_t)b * LSEQ * DDIM;

    uint32_t aS[NSTG], bS[NSTG];
    #pragma unroll
    for (int s = 0; s < NSTG; s++) {
        aS[s] = sb + s * (A_STG + B_STG);
        bS[s] = aS[s] + A_STG;
    }

    // ldmatrix per-thread base offsets
    const int rowA = warpM * 64 + (lane & 7) + ((lane >> 3) & 1) * 8;
    const int colA = ((lane >> 4) & 1) * 8;          // k-elems
    const int rowB = warpN * 64 + (lane & 7) + ((lane >> 4) & 1) * 8;
    const int colB = ((lane >> 3) & 1) * 8;

    uint32_t acc[4][8][2];                 // f16x2 accumulators (raw dots)
    #pragma unroll
    for (int i = 0; i < 4; i++)
        #pragma unroll
        for (int j = 0; j < 8; j++) { acc[i][j][0] = 0u; acc[i][j][1] = 0u; }

    auto load_stage = [&](int s, int kb) {
        int k0 = kb * BK;
        #pragma unroll
        for (int i = 0; i < 2; i++) {                // A: 512 16B-chunks
            int j = tid + i * 256;
            int row = j >> 2;
            int c16 = (j & 3) * 16;
            cp_async16(aS[s] + row * PITCH_B + c16,
                       Qb + (size_t)(mBase + row) * DDIM + k0 + c16 / 2);
        }
        #pragma unroll
        for (int i = 0; i < 4; i++) {                // B: 1024 chunks
            int j = tid + i * 256;
            int row = j >> 2;
            int c16 = (j & 3) * 16;
            cp_async16(bS[s] + row * PITCH_B + c16,
                       Mb + (size_t)(nBase + row) * DDIM + k0 + c16 / 2);
        }
        asm volatile("cp.async.commit_group;\n");
    };

    // prologue: 2 stages in flight
    load_stage(0, 0);
    load_stage(1, 1);

    for (int kb = 0; kb < NKB; kb++) {
        int s = kb % NSTG;
        if (kb + 2 < NKB) asm volatile("cp.async.wait_group 1;\n");
        else              asm volatile("cp.async.wait_group 0;\n");
        __syncthreads();

        if (kb + 2 < NKB) load_stage((kb + 2) % NSTG, kb + 2);

        uint32_t aBase = aS[s] + rowA * PITCH_B + colA * 2;
        uint32_t bBase = bS[s] + rowB * PITCH_B + colB * 2;
        #pragma unroll
        for (int ks = 0; ks < 2; ks++) {             // two k16 slabs
            uint32_t af[4][4];
            #pragma unroll
            for (int mt = 0; mt < 4; mt++)
                LDSM_X4(af[mt], aBase + mt * (16 * PITCH_B) + ks * 32);
            #pragma unroll
            for (int nh = 0; nh < 2; nh++) {         // 2 B-halves (32 cols each)
                uint32_t bf[2][4];
                #pragma unroll
                for (int n2 = 0; n2 < 2; n2++)
                    LDSM_X4(bf[n2], bBase + (nh * 32 + n2 * 16) * PITCH_B + ks * 32);
                #pragma unroll
                for (int mt = 0; mt < 4; mt++)
                    #pragma unroll
                    for (int nt = 0; nt < 4; nt++)
                        MMAF16(acc[mt][nh * 4 + nt], af[mt], &bf[nt >> 1][(nt & 1) * 2]);
            }
        }
    }

    // Epilogue: direct fp16 stores + per-(row, 64col-block) max plain stores
    __half* Srow = g_S + (size_t)b * LSEQ * LSEQ;
    const int ntile = (nBase >> 6) + warpN;          // 0..31, unique per warp
    #pragma unroll
    for (int mt = 0; mt < 4; mt++) {
        float vmax0 = -1e30f, vmax1 = -1e30f;
        #pragma unroll
        for (int j = 0; j < 8; j++) {
            int row = mBase + warpM * 64 + mt * 16 + g;
            int col = nBase + warpN * 64 + j * 8 + 2 * t;
            *(uint32_t*)(Srow + (size_t)(row    ) * LSEQ + col) = acc[mt][j][0];
            *(uint32_t*)(Srow + (size_t)(row + 8) * LSEQ + col) = acc[mt][j][1];
            __half2 v0 = *(__half2*)&acc[mt][j][0];
            __half2 v1 = *(__half2*)&acc[mt][j][1];
            vmax0 = fmaxf(vmax0, fmaxf(__low2float(v0), __high2float(v0)));
            vmax1 = fmaxf(vmax1, fmaxf(__low2float(v1), __high2float(v1)));
        }
        // reduce across the 4 t-threads of each group (same output rows)
        #pragma unroll
        for (int o = 1; o <= 2; o <<= 1) {
            vmax0 = fmaxf(vmax0, __shfl_xor_sync(0xffffffffu, vmax0, o));
            vmax1 = fmaxf(vmax1, __shfl_xor_sync(0xffffffffu, vmax1, o));
        }
        if (t == 0) {
            int row = mBase + warpM * 64 + mt * 16 + g;
            g_bmax[((size_t)b * LSEQ + row    ) * 32 + ntile] = __float2half(vmax0);
            g_bmax[((size_t)b * LSEQ + row + 8) * 32 + ntile] = __float2half(vmax1);
        }
    }
}

// ---------------------------------------------------------------------------
// Kernel 3: per-row refine. Row max + candidate blocks from g_bmax (64 B),
// scan only flagged 64-score blocks (~1 per row). nc==1 fast path (exact);
// warp-parallel exact fp32 dots otherwise. Candidate sets identical to the
// full-scan version (same threshold values, same scores).
// ---------------------------------------------------------------------------
#define CAP 64
#define MARGIN 1.0f

__global__ __launch_bounds__(256) void refine_kernel(const float* __restrict__ Q,
                                                     const float* __restrict__ Mem,
                                                     float* __restrict__ Out) {
    const int b = blockIdx.y, q = blockIdx.x, tid = threadIdx.x;
    const int lane = tid & 31, warp = tid >> 5;
    const __half* srow = g_S + ((size_t)b * LSEQ + q) * LSEQ;

    __shared__ int      s_cnt;
    __shared__ float    s_thr;
    __shared__ uint32_t s_flags;
    __shared__ int      s_idx[CAP];
    __shared__ float    s_dot[CAP];
    __shared__ float    s_w[CAP];

    // 1) block maxes -> row max, threshold, flagged blocks (warp 0)
    if (warp == 0) {
        float v = __half2float(g_bmax[((size_t)b * LSEQ + q) * 32 + lane]);
        float mx = v;
        #pragma unroll
        for (int o = 16; o; o >>= 1) mx = fmaxf(mx, __shfl_xor_sync(0xffffffffu, mx, o));
        float thr = mx - MARGIN;
        uint32_t fl = __ballot_sync(0xffffffffu, v >= thr);
        if (lane == 0) { s_thr = thr; s_flags = fl; s_cnt = 0; }
    }
    __syncthreads();

    // 2) candidate scan over flagged 64-score blocks only
    {
        float thr = s_thr;
        uint32_t flags = s_flags;
        int nf = __popc(flags);
        int grp = tid >> 6;                  // 4 groups of 64 threads
        int t64 = tid & 63;
        for (int fi = grp; fi < nf; fi += 4) {
            int blk = __fns(flags, 0, fi + 1);
            int k = blk * 64 + t64;
            if (__half2float(srow[k]) >= thr) {
                int p = atomicAdd(&s_cnt, 1);
                if (p < CAP) s_idx[p] = k;
            }
        }
    }
    __syncthreads();
    int nc = min(s_cnt, CAP);

    // 3) fast path: single candidate -> output = that memory row exactly
    if (nc == 1) {
        const float4* src = (const float4*)(Mem + ((size_t)b * LSEQ + s_idx[0]) * DDIM);
        float4* dst = (float4*)(Out + ((size_t)b * LSEQ + q) * DDIM);
        dst[tid] = src[tid];                 // 256 threads x float4 = 1024
        return;
    }

    if (tid == 0) {                          // sort for determinism
        for (int i = 1; i < nc; i++) {
            int v = s_idx[i], j = i - 1;
            while (j >= 0 && s_idx[j] > v) { s_idx[j + 1] = s_idx[j]; j--; }
            s_idx[j + 1] = v;
        }
    }
    __syncthreads();

    // 4) exact fp32 dots, one warp per candidate
    const float* qrow = Q + ((size_t)b * LSEQ + q) * DDIM;
    for (int j = warp; j < nc; j += 8) {
        const float* mrow = Mem + ((size_t)b * LSEQ + s_idx[j]) * DDIM;
        float p = 0.f;
        #pragma unroll 4
        for (int d = lane; d < DDIM; d += 32) p += qrow[d] * mrow[d];
        #pragma unroll
        for (int o = 16; o; o >>= 1) p += __shfl_xor_sync(0xffffffffu, p, o);
        if (lane == 0) s_dot[j] = p;
    }
    __syncthreads();

    // 5) exact softmax over candidates
    if (tid == 0) {
        float dm = -1e30f;
        for (int j = 0; j < nc; j++) dm = fmaxf(dm, s_dot[j]);
        float sum = 0.f;
        for (int j = 0; j < nc; j++) {
            float w = expf((s_dot[j] - dm) * TAW_INV);
            s_w[j] = w; sum += w;
        }
        float inv = 1.0f / sum;
        for (int j = 0; j < nc; j++) s_w[j] *= inv;
    }
    __syncthreads();

    // 6) output mixture (float4 vectorized)
    const float4* M4 = (const float4*)Mem;
    float4* dst = (float4*)(Out + ((size_t)b * LSEQ + q) * DDIM);
    float4 a = make_float4(0.f, 0.f, 0.f, 0.f);
    for (int j = 0; j < nc; j++) {
        float w = s_w[j];
        float4 v = M4[(((size_t)b * LSEQ + s_idx[j]) * DDIM >> 2) + tid];
        a.x += w * v.x; a.y += w * v.y; a.z += w * v.z; a.w += w * v.w;
    }
    dst[tid] = a;
}

// ---------------------------------------------------------------------------
extern "C" void kernel_launch(void* const* d_in, const int* in_sizes, int n_in,
                              void* d_out, int out_size) {
    const float* q = (const float*)d_in[0];
    const float* m = (const float*)d_in[1];
    float* out = (float*)d_out;

    // Host-side attribute set (not a stream op -> capture-safe)
    cudaFuncSetAttribute(qk_gemm_kernel,
                         cudaFuncAttributeMaxDynamicSharedMemorySize, QK_DSMEM);

    size_t n4 = (size_t)BATCH * LSEQ * DDIM / 4;   // 4,194,304
    convert_kernel<<<(unsigned)((n4 + 255) / 256), 256>>>(q, m);

    dim3 gg(LSEQ / BN, LSEQ / BM, BATCH);          // 8 x 16 x 8
    qk_gemm_kernel<<<gg, 256, QK_DSMEM>>>();

    dim3 rg(LSEQ, BATCH);
    refine_kernel<<<rg, 256>>>(q, m, out);
}